// round 5
// baseline (speedup 1.0000x reference)
#include <cuda_runtime.h>
#include <stdint.h>

#define NMAX 50000
#define EMAX 800000
#define DIM 128

// ---------------- scratch (static device globals; no allocation) ----------------
__device__ float g_buf0[(size_t)NMAX * DIM];   // GEMM output H
__device__ float g_buf1[(size_t)NMAX * DIM];   // aggregated / activation buffer
__device__ float g_h3[NMAX * 2];
__device__ float g_dis[NMAX];
__device__ int   g_cnt[NMAX];
__device__ int   g_starts[NMAX];
__device__ int   g_cursor[NMAX];
__device__ int   g_csr_src[EMAX];
__device__ float g_csr_w[EMAX];

// ---------------- JAX Threefry-2x32 (20 rounds) ----------------
__host__ __device__ __forceinline__ void tf2x32(uint32_t k0, uint32_t k1,
                                                uint32_t x0, uint32_t x1,
                                                uint32_t& o0, uint32_t& o1) {
    uint32_t ks2 = k0 ^ k1 ^ 0x1BD11BDAu;
    x0 += k0; x1 += k1;
#define TFROT(a, b, r) { a += b; b = ((b << (r)) | (b >> (32 - (r)))); b ^= a; }
    TFROT(x0, x1, 13) TFROT(x0, x1, 15) TFROT(x0, x1, 26) TFROT(x0, x1, 6)
    x0 += k1;  x1 += ks2 + 1u;
    TFROT(x0, x1, 17) TFROT(x0, x1, 29) TFROT(x0, x1, 16) TFROT(x0, x1, 24)
    x0 += ks2; x1 += k0 + 2u;
    TFROT(x0, x1, 13) TFROT(x0, x1, 15) TFROT(x0, x1, 26) TFROT(x0, x1, 6)
    x0 += k0;  x1 += k1 + 3u;
    TFROT(x0, x1, 17) TFROT(x0, x1, 29) TFROT(x0, x1, 16) TFROT(x0, x1, 24)
    x0 += k1;  x1 += ks2 + 4u;
    TFROT(x0, x1, 13) TFROT(x0, x1, 15) TFROT(x0, x1, 26) TFROT(x0, x1, 6)
    x0 += ks2; x1 += k0 + 5u;
#undef TFROT
    o0 = x0; o1 = x1;
}

// ---------------- graph prep ----------------
__global__ void k_zero_cnt(int n) {
    int i = blockIdx.x * blockDim.x + threadIdx.x;
    if (i < n) g_cnt[i] = 0;
}

__global__ void k_count(const int* __restrict__ ei, int E) {
    int e = blockIdx.x * blockDim.x + threadIdx.x;
    if (e >= E) return;
    int d = ei[E + e];
    atomicAdd(&g_cnt[d], 1);
}

__global__ void k_dis(int n) {
    int i = blockIdx.x * blockDim.x + threadIdx.x;
    if (i < n) g_dis[i] = rsqrtf((float)(g_cnt[i] + 1));
}

// single-block exclusive scan of g_cnt -> g_starts (+ cursor copy)
__global__ void k_scan(int n) {
    __shared__ int sd[1024];
    __shared__ int carry;
    int tid = threadIdx.x;
    if (tid == 0) carry = 0;
    __syncthreads();
    for (int base = 0; base < n; base += 1024) {
        int i = base + tid;
        int v = (i < n) ? g_cnt[i] : 0;
        sd[tid] = v;
        __syncthreads();
        for (int off = 1; off < 1024; off <<= 1) {
            int t2 = (tid >= off) ? sd[tid - off] : 0;
            __syncthreads();
            sd[tid] += t2;
            __syncthreads();
        }
        int excl = sd[tid] - v;
        if (i < n) { g_starts[i] = carry + excl; g_cursor[i] = carry + excl; }
        __syncthreads();
        if (tid == 0) carry += sd[1023];
        __syncthreads();
    }
}

__global__ void k_scatter(const int* __restrict__ ei, int E) {
    int e = blockIdx.x * blockDim.x + threadIdx.x;
    if (e >= E) return;
    int s = ei[e];
    int d = ei[E + e];
    int pos = atomicAdd(&g_cursor[d], 1);
    g_csr_src[pos] = s;
    g_csr_w[pos] = g_dis[s] * g_dis[d];
}

// ---------------- GEMM: g_buf0[nrows,128] = X[nrows,128] @ W[128,128] ----------------
// X = Xext (layer 1) or g_buf1 (layer 2). 64 rows x 128 cols per block,
// 256 threads, 4x8 register tile, K chunked by 32 (static smem ~25 KB).
__global__ void k_gemm128(const float* __restrict__ Xext,
                          const float* __restrict__ W, int nrows) {
    __shared__ float Ws[32 * 128];      // chunk of W: [32 k][128 cols]
    __shared__ float Xs[32 * 68];       // transposed X chunk: [32 k][64 rows +pad]

    const float* X = Xext ? Xext : g_buf1;
    float* H = g_buf0;

    int t = threadIdx.x;
    int row0 = blockIdx.x * 64;
    int tx = t & 15;    // col group (8 cols)
    int ty = t >> 4;    // row group (4 rows)

    float acc[4][8];
#pragma unroll
    for (int i = 0; i < 4; i++)
#pragma unroll
        for (int j = 0; j < 8; j++) acc[i][j] = 0.f;

    for (int c = 0; c < 4; c++) {       // K chunks of 32
        // load W chunk: rows c*32..c*32+31, 4096 floats = 1024 float4
        const float4* Wg = (const float4*)(W + c * 32 * 128);
        float4* Wsv = (float4*)Ws;
#pragma unroll
        for (int i = 0; i < 4; i++) Wsv[t + i * 256] = Wg[t + i * 256];

        // load X chunk transposed: 64 rows x 32 cols = 512 float4
#pragma unroll
        for (int i = 0; i < 2; i++) {
            int q = t + i * 256;              // 0..511
            int r = q >> 3;                   // 0..63
            int kk = (q & 7) * 4;             // 0..28
            float4 v = make_float4(0.f, 0.f, 0.f, 0.f);
            if (row0 + r < nrows)
                v = *(const float4*)(X + (size_t)(row0 + r) * DIM + c * 32 + kk);
            Xs[(kk + 0) * 68 + r] = v.x;
            Xs[(kk + 1) * 68 + r] = v.y;
            Xs[(kk + 2) * 68 + r] = v.z;
            Xs[(kk + 3) * 68 + r] = v.w;
        }
        __syncthreads();

#pragma unroll
        for (int k = 0; k < 32; k++) {
            float4 xv = *(const float4*)&Xs[k * 68 + ty * 4];
            float4 wa = *(const float4*)&Ws[k * 128 + tx * 8];
            float4 wb = *(const float4*)&Ws[k * 128 + tx * 8 + 4];
            float xr[4] = {xv.x, xv.y, xv.z, xv.w};
            float wr[8] = {wa.x, wa.y, wa.z, wa.w, wb.x, wb.y, wb.z, wb.w};
#pragma unroll
            for (int i = 0; i < 4; i++)
#pragma unroll
                for (int j = 0; j < 8; j++) acc[i][j] += xr[i] * wr[j];
        }
        __syncthreads();
    }

#pragma unroll
    for (int i = 0; i < 4; i++) {
        int r = row0 + ty * 4 + i;
        if (r < nrows) {
            float4 o0 = make_float4(acc[i][0], acc[i][1], acc[i][2], acc[i][3]);
            float4 o1 = make_float4(acc[i][4], acc[i][5], acc[i][6], acc[i][7]);
            *(float4*)(H + (size_t)r * DIM + tx * 8) = o0;
            *(float4*)(H + (size_t)r * DIM + tx * 8 + 4) = o1;
        }
    }
}

// ------- aggregation: g_buf1[v] = b + dis[v]^2*g_buf0[v] + sum_e w*g_buf0[src] -------
__global__ void k_agg128(const float* __restrict__ bias, int n) {
    const float* H = g_buf0;
    float* OUT = g_buf1;
    int g = blockIdx.x * blockDim.x + threadIdx.x;
    int v = g >> 5;
    if (v >= n) return;
    int lane = g & 31;
    int s0 = g_starts[v];
    int cnt = g_cnt[v];

    float4 acc = make_float4(0.f, 0.f, 0.f, 0.f);
    for (int base = 0; base < cnt; base += 32) {
        int si = 0; float wi = 0.f;
        if (base + lane < cnt) {
            si = g_csr_src[s0 + base + lane];
            wi = g_csr_w[s0 + base + lane];
        }
        int m = min(32, cnt - base);
        for (int j = 0; j < m; j++) {
            int s = __shfl_sync(0xffffffffu, si, j);
            float w = __shfl_sync(0xffffffffu, wi, j);
            float4 hv = *(const float4*)(H + (size_t)s * DIM + lane * 4);
            acc.x += w * hv.x; acc.y += w * hv.y;
            acc.z += w * hv.z; acc.w += w * hv.w;
        }
    }
    float dv = g_dis[v];
    float ws = dv * dv;
    float4 hv = *(const float4*)(H + (size_t)v * DIM + lane * 4);
    float4 bv = *(const float4*)(bias + lane * 4);
    acc.x += ws * hv.x + bv.x;
    acc.y += ws * hv.y + bv.y;
    acc.z += ws * hv.z + bv.z;
    acc.w += ws * hv.w + bv.w;
    *(float4*)(OUT + (size_t)v * DIM + lane * 4) = acc;
}

// ------- leaky_relu + exact-JAX dropout (partitionable threefry), on g_buf1 -------
__global__ void k_elem(int total, uint32_t ka, uint32_t kb) {
    int i = blockIdx.x * blockDim.x + threadIdx.x;
    if (i >= total) return;
    float v = g_buf1[i];
    v = (v >= 0.f) ? v : 0.01f * v;
    uint32_t y0, y1;
    tf2x32(ka, kb, 0u, (uint32_t)i, y0, y1);
    uint32_t bits = y0 ^ y1;                       // partitionable 32-bit path
    float u = __uint_as_float((bits >> 9) | 0x3f800000u) - 1.0f;
    g_buf1[i] = (u < 0.5f) ? (v + v) : 0.0f;       // keep-prob 0.5 -> x/0.5
}

// ---------------- layer 3: g_h3 = g_buf1[N,128] @ W3[128,2], warp per node ----------------
__global__ void k_gemm3(const float* __restrict__ W3, int n) {
    const float* X = g_buf1;
    int g = blockIdx.x * blockDim.x + threadIdx.x;
    int v = g >> 5;
    if (v >= n) return;
    int lane = g & 31;
    float4 xv = *(const float4*)(X + (size_t)v * DIM + lane * 4);
    float4 wA = *(const float4*)(W3 + lane * 8);       // rows lane*4, lane*4+1
    float4 wB = *(const float4*)(W3 + lane * 8 + 4);   // rows lane*4+2, lane*4+3
    float a0 = xv.x * wA.x + xv.y * wA.z + xv.z * wB.x + xv.w * wB.z;
    float a1 = xv.x * wA.y + xv.y * wA.w + xv.z * wB.y + xv.w * wB.w;
#pragma unroll
    for (int off = 16; off > 0; off >>= 1) {
        a0 += __shfl_xor_sync(0xffffffffu, a0, off);
        a1 += __shfl_xor_sync(0xffffffffu, a1, off);
    }
    if (lane == 0) { g_h3[v * 2] = a0; g_h3[v * 2 + 1] = a1; }
}

// ---------------- final aggregation + bias + log_softmax ----------------
__global__ void k_final(const float* __restrict__ b3, float* __restrict__ out, int n) {
    int v = blockIdx.x * blockDim.x + threadIdx.x;
    if (v >= n) return;
    int s0 = g_starts[v];
    int e0 = s0 + g_cnt[v];
    float a0 = 0.f, a1 = 0.f;
    for (int i = s0; i < e0; i++) {
        int s = g_csr_src[i];
        float w = g_csr_w[i];
        a0 += w * g_h3[s * 2];
        a1 += w * g_h3[s * 2 + 1];
    }
    float dv = g_dis[v];
    float ws = dv * dv;
    a0 += ws * g_h3[v * 2]     + b3[0];
    a1 += ws * g_h3[v * 2 + 1] + b3[1];
    float m = fmaxf(a0, a1);
    float lse = m + logf(expf(a0 - m) + expf(a1 - m));
    out[v * 2]     = a0 - lse;
    out[v * 2 + 1] = a1 - lse;
}

// ---------------- launch (pure kernel launches; graph-capture safe) ----------------
extern "C" void kernel_launch(void* const* d_in, const int* in_sizes, int n_in,
                              void* d_out, int out_size) {
    const float* x  = (const float*)d_in[0];
    const int*   ei = (const int*)d_in[1];     // int32 (JAX x64 disabled)
    const float* W1 = (const float*)d_in[2];
    const float* b1 = (const float*)d_in[3];
    const float* W2 = (const float*)d_in[4];
    const float* b2 = (const float*)d_in[5];
    const float* W3 = (const float*)d_in[6];
    const float* b3 = (const float*)d_in[7];
    float* out = (float*)d_out;

    int n = in_sizes[0] / DIM;      // 50000
    int E = in_sizes[1] / 2;        // 800000

    // JAX: dkey = key(42); k1, k2 = split(dkey)  [partitionable fold-like split]
    uint32_t k1a, k1b, k2a, k2b;
    tf2x32(0u, 42u, 0u, 0u, k1a, k1b);
    tf2x32(0u, 42u, 0u, 1u, k2a, k2b);

    int nb_n  = (n + 255) / 256;
    int nb_e  = (E + 255) / 256;
    int nb_w  = (n * 32 + 255) / 256;   // warp-per-node grids
    int nb_el = (n * DIM + 255) / 256;
    int nb_g  = (n + 63) / 64;

    // graph prep (once per launch, reused by all 3 layers)
    k_zero_cnt<<<nb_n, 256>>>(n);
    k_count<<<nb_e, 256>>>(ei, E);
    k_dis<<<nb_n, 256>>>(n);
    k_scan<<<1, 1024>>>(n);
    k_scatter<<<nb_e, 256>>>(ei, E);

    // layer 1
    k_gemm128<<<nb_g, 256>>>(x, W1, n);
    k_agg128<<<nb_w, 256>>>(b1, n);
    k_elem<<<nb_el, 256>>>(n * DIM, k1a, k1b);

    // layer 2
    k_gemm128<<<nb_g, 256>>>(nullptr, W2, n);
    k_agg128<<<nb_w, 256>>>(b2, n);
    k_elem<<<nb_el, 256>>>(n * DIM, k2a, k2b);

    // layer 3 + log_softmax
    k_gemm3<<<nb_w, 256>>>(W3, n);
    k_final<<<nb_n, 256>>>(b3, out, n);
}

// round 8
// speedup vs baseline: 1.5490x; 1.5490x over previous
#include <cuda_runtime.h>
#include <stdint.h>

#define NMAX 50000
#define EMAX 800000
#define DIM 128

// ---------------- scratch (static device globals; no allocation) ----------------
__device__ float g_buf0[(size_t)NMAX * DIM];   // GEMM output H
__device__ float g_buf1[(size_t)NMAX * DIM];   // aggregated / activation buffer
__device__ float g_h3[NMAX * 2];
__device__ float g_dis[NMAX];
__device__ int   g_cnt[NMAX];
__device__ int   g_starts[NMAX];
__device__ int   g_cursor[NMAX];
__device__ int   g_csr_src[EMAX];
__device__ float g_csr_w[EMAX];
__device__ int   g_total;

// ---------------- JAX Threefry-2x32 (20 rounds) ----------------
__host__ __device__ __forceinline__ void tf2x32(uint32_t k0, uint32_t k1,
                                                uint32_t x0, uint32_t x1,
                                                uint32_t& o0, uint32_t& o1) {
    uint32_t ks2 = k0 ^ k1 ^ 0x1BD11BDAu;
    x0 += k0; x1 += k1;
#define TFROT(a, b, r) { a += b; b = ((b << (r)) | (b >> (32 - (r)))); b ^= a; }
    TFROT(x0, x1, 13) TFROT(x0, x1, 15) TFROT(x0, x1, 26) TFROT(x0, x1, 6)
    x0 += k1;  x1 += ks2 + 1u;
    TFROT(x0, x1, 17) TFROT(x0, x1, 29) TFROT(x0, x1, 16) TFROT(x0, x1, 24)
    x0 += ks2; x1 += k0 + 2u;
    TFROT(x0, x1, 13) TFROT(x0, x1, 15) TFROT(x0, x1, 26) TFROT(x0, x1, 6)
    x0 += k0;  x1 += k1 + 3u;
    TFROT(x0, x1, 17) TFROT(x0, x1, 29) TFROT(x0, x1, 16) TFROT(x0, x1, 24)
    x0 += k1;  x1 += ks2 + 4u;
    TFROT(x0, x1, 13) TFROT(x0, x1, 15) TFROT(x0, x1, 26) TFROT(x0, x1, 6)
    x0 += ks2; x1 += k0 + 5u;
#undef TFROT
    o0 = x0; o1 = x1;
}

// dropout decision for flat element index i under key (ka,kb): true => keep
__device__ __forceinline__ bool drop_keep(uint32_t ka, uint32_t kb, uint32_t i) {
    uint32_t y0, y1;
    tf2x32(ka, kb, 0u, i, y0, y1);
    uint32_t bits = y0 ^ y1;
    float u = __uint_as_float((bits >> 9) | 0x3f800000u) - 1.0f;
    return u < 0.5f;
}

// ---------------- graph prep ----------------
__global__ void k_zero_cnt(int n) {
    int i = blockIdx.x * blockDim.x + threadIdx.x;
    if (i == 0) g_total = 0;
    if (i < n) g_cnt[i] = 0;
}

__global__ void k_count(const int* __restrict__ ei, int E) {
    int e = blockIdx.x * blockDim.x + threadIdx.x;
    if (e >= E) return;
    int d = ei[E + e];
    atomicAdd(&g_cnt[d], 1);
}

// dis + atomic region reservation (replaces the serial scan: CSR row order is
// irrelevant, only disjointness matters)
__global__ void k_disres(int n) {
    int i = blockIdx.x * blockDim.x + threadIdx.x;
    if (i >= n) return;
    int c = g_cnt[i];
    g_dis[i] = rsqrtf((float)(c + 1));
    int st = atomicAdd(&g_total, c);
    g_starts[i] = st;
    g_cursor[i] = st;
}

__global__ void k_scatter(const int* __restrict__ ei, int E) {
    int e = blockIdx.x * blockDim.x + threadIdx.x;
    if (e >= E) return;
    int s = ei[e];
    int d = ei[E + e];
    int pos = atomicAdd(&g_cursor[d], 1);
    g_csr_src[pos] = s;
    g_csr_w[pos] = g_dis[s] * g_dis[d];
}

// ---------------- GEMM: g_buf0[nrows,128] = X[nrows,128] @ W[128,128] ----------------
// 128 rows x 128 cols per block, 256 threads, 8x8 register tile, K chunked by 16.
#define XS_STRIDE 136   // floats; multiple of 4 for aligned float4 reads

__global__ void k_gemm128(const float* __restrict__ Xext,
                          const float* __restrict__ W, int nrows) {
    __shared__ float Ws[16 * 128];            // [16 k][128 cols]
    __shared__ float Xs[16 * XS_STRIDE];      // transposed: [16 k][128 rows]

    const float* X = Xext ? Xext : g_buf1;
    float* H = g_buf0;

    int t = threadIdx.x;
    int row0 = blockIdx.x * 128;
    int tx = t & 15;    // col group (8 cols)
    int ty = t >> 4;    // row group (8 rows)

    float acc[8][8];
#pragma unroll
    for (int i = 0; i < 8; i++)
#pragma unroll
        for (int j = 0; j < 8; j++) acc[i][j] = 0.f;

    for (int c = 0; c < 8; c++) {             // K chunks of 16
        // W chunk: 16 x 128 = 512 float4
        const float4* Wg = (const float4*)(W + c * 16 * 128);
        float4* Wsv = (float4*)Ws;
        Wsv[t] = Wg[t];
        Wsv[t + 256] = Wg[t + 256];

        // X chunk transposed: 128 rows x 16 k = 512 float4
#pragma unroll
        for (int i = 0; i < 2; i++) {
            int q = t + i * 256;              // 0..511
            int r = q >> 2;                   // 0..127
            int kk = (q & 3) * 4;             // 0,4,8,12
            float4 v = make_float4(0.f, 0.f, 0.f, 0.f);
            if (row0 + r < nrows)
                v = *(const float4*)(X + (size_t)(row0 + r) * DIM + c * 16 + kk);
            Xs[(kk + 0) * XS_STRIDE + r] = v.x;
            Xs[(kk + 1) * XS_STRIDE + r] = v.y;
            Xs[(kk + 2) * XS_STRIDE + r] = v.z;
            Xs[(kk + 3) * XS_STRIDE + r] = v.w;
        }
        __syncthreads();

#pragma unroll
        for (int k = 0; k < 16; k++) {
            float4 xa = *(const float4*)&Xs[k * XS_STRIDE + ty * 8];
            float4 xb = *(const float4*)&Xs[k * XS_STRIDE + ty * 8 + 4];
            float4 wa = *(const float4*)&Ws[k * 128 + tx * 8];
            float4 wb = *(const float4*)&Ws[k * 128 + tx * 8 + 4];
            float xr[8] = {xa.x, xa.y, xa.z, xa.w, xb.x, xb.y, xb.z, xb.w};
            float wr[8] = {wa.x, wa.y, wa.z, wa.w, wb.x, wb.y, wb.z, wb.w};
#pragma unroll
            for (int i = 0; i < 8; i++)
#pragma unroll
                for (int j = 0; j < 8; j++) acc[i][j] += xr[i] * wr[j];
        }
        __syncthreads();
    }

#pragma unroll
    for (int i = 0; i < 8; i++) {
        int r = row0 + ty * 8 + i;
        if (r < nrows) {
            float4 o0 = make_float4(acc[i][0], acc[i][1], acc[i][2], acc[i][3]);
            float4 o1 = make_float4(acc[i][4], acc[i][5], acc[i][6], acc[i][7]);
            *(float4*)(H + (size_t)r * DIM + tx * 8) = o0;
            *(float4*)(H + (size_t)r * DIM + tx * 8 + 4) = o1;
        }
    }
}

// ------- aggregation + bias + (optional) leaky_relu + exact-JAX dropout -------
// g_buf1[v] = f( b + dis[v]^2*g_buf0[v] + sum_e w*g_buf0[src] )
__global__ void k_agg128(const float* __restrict__ bias, int n,
                         int doAct, uint32_t ka, uint32_t kb) {
    const float* H = g_buf0;
    float* OUT = g_buf1;
    int g = blockIdx.x * blockDim.x + threadIdx.x;
    int v = g >> 5;
    if (v >= n) return;
    int lane = g & 31;
    int s0 = g_starts[v];
    int cnt = g_cnt[v];

    float4 acc = make_float4(0.f, 0.f, 0.f, 0.f);
    for (int base = 0; base < cnt; base += 32) {
        int si = 0; float wi = 0.f;
        if (base + lane < cnt) {
            si = g_csr_src[s0 + base + lane];
            wi = g_csr_w[s0 + base + lane];
        }
        int m = min(32, cnt - base);
        for (int j = 0; j < m; j++) {
            int s = __shfl_sync(0xffffffffu, si, j);
            float w = __shfl_sync(0xffffffffu, wi, j);
            float4 hv = *(const float4*)(H + (size_t)s * DIM + lane * 4);
            acc.x += w * hv.x; acc.y += w * hv.y;
            acc.z += w * hv.z; acc.w += w * hv.w;
        }
    }
    float dv = g_dis[v];
    float ws = dv * dv;
    float4 hv = *(const float4*)(H + (size_t)v * DIM + lane * 4);
    float4 bv = *(const float4*)(bias + lane * 4);
    acc.x += ws * hv.x + bv.x;
    acc.y += ws * hv.y + bv.y;
    acc.z += ws * hv.z + bv.z;
    acc.w += ws * hv.w + bv.w;

    if (doAct) {
        uint32_t i0 = (uint32_t)v * DIM + lane * 4;
        float a[4] = {acc.x, acc.y, acc.z, acc.w};
#pragma unroll
        for (int c2 = 0; c2 < 4; c2++) {
            float vv = a[c2];
            vv = (vv >= 0.f) ? vv : 0.01f * vv;          // leaky_relu
            a[c2] = drop_keep(ka, kb, i0 + c2) ? (vv + vv) : 0.f;  // p=0.5
        }
        acc.x = a[0]; acc.y = a[1]; acc.z = a[2]; acc.w = a[3];
    }
    *(float4*)(OUT + (size_t)v * DIM + lane * 4) = acc;
}

// ---------------- layer 3: g_h3 = g_buf1[N,128] @ W3[128,2], warp per node ----------------
__global__ void k_gemm3(const float* __restrict__ W3, int n) {
    const float* X = g_buf1;
    int g = blockIdx.x * blockDim.x + threadIdx.x;
    int v = g >> 5;
    if (v >= n) return;
    int lane = g & 31;
    float4 xv = *(const float4*)(X + (size_t)v * DIM + lane * 4);
    float4 wA = *(const float4*)(W3 + lane * 8);
    float4 wB = *(const float4*)(W3 + lane * 8 + 4);
    float a0 = xv.x * wA.x + xv.y * wA.z + xv.z * wB.x + xv.w * wB.z;
    float a1 = xv.x * wA.y + xv.y * wA.w + xv.z * wB.y + xv.w * wB.w;
#pragma unroll
    for (int off = 16; off > 0; off >>= 1) {
        a0 += __shfl_xor_sync(0xffffffffu, a0, off);
        a1 += __shfl_xor_sync(0xffffffffu, a1, off);
    }
    if (lane == 0) { g_h3[v * 2] = a0; g_h3[v * 2 + 1] = a1; }
}

// ---------------- final aggregation + bias + log_softmax ----------------
__global__ void k_final(const float* __restrict__ b3, float* __restrict__ out, int n) {
    int v = blockIdx.x * blockDim.x + threadIdx.x;
    if (v >= n) return;
    int s0 = g_starts[v];
    int e0 = s0 + g_cnt[v];
    float a0 = 0.f, a1 = 0.f;
    for (int i = s0; i < e0; i++) {
        int s = g_csr_src[i];
        float w = g_csr_w[i];
        a0 += w * g_h3[s * 2];
        a1 += w * g_h3[s * 2 + 1];
    }
    float dv = g_dis[v];
    float ws = dv * dv;
    a0 += ws * g_h3[v * 2]     + b3[0];
    a1 += ws * g_h3[v * 2 + 1] + b3[1];
    float m = fmaxf(a0, a1);
    float lse = m + logf(expf(a0 - m) + expf(a1 - m));
    out[v * 2]     = a0 - lse;
    out[v * 2 + 1] = a1 - lse;
}

// ---------------- launch (pure kernel launches; graph-capture safe) ----------------
extern "C" void kernel_launch(void* const* d_in, const int* in_sizes, int n_in,
                              void* d_out, int out_size) {
    const float* x  = (const float*)d_in[0];
    const int*   ei = (const int*)d_in[1];     // int32 (JAX x64 disabled)
    const float* W1 = (const float*)d_in[2];
    const float* b1 = (const float*)d_in[3];
    const float* W2 = (const float*)d_in[4];
    const float* b2 = (const float*)d_in[5];
    const float* W3 = (const float*)d_in[6];
    const float* b3 = (const float*)d_in[7];
    float* out = (float*)d_out;

    int n = in_sizes[0] / DIM;      // 50000
    int E = in_sizes[1] / 2;        // 800000

    // JAX: dkey = key(42); k1, k2 = split(dkey)  [partitionable fold-like split]
    uint32_t k1a, k1b, k2a, k2b;
    tf2x32(0u, 42u, 0u, 0u, k1a, k1b);
    tf2x32(0u, 42u, 0u, 1u, k2a, k2b);

    int nb_n = (n + 255) / 256;
    int nb_e = (E + 255) / 256;
    int nb_w = (n * 32 + 255) / 256;   // warp-per-node grids
    int nb_g = (n + 127) / 128;

    // graph prep
    k_zero_cnt<<<nb_n, 256>>>(n);
    k_count<<<nb_e, 256>>>(ei, E);
    k_disres<<<nb_n, 256>>>(n);
    k_scatter<<<nb_e, 256>>>(ei, E);

    // layer 1 (agg fuses bias + leaky_relu + dropout)
    k_gemm128<<<nb_g, 256>>>(x, W1, n);
    k_agg128<<<nb_w, 256>>>(b1, n, 1, k1a, k1b);

    // layer 2
    k_gemm128<<<nb_g, 256>>>(nullptr, W2, n);
    k_agg128<<<nb_w, 256>>>(b2, n, 1, k2a, k2b);

    // layer 3 + log_softmax
    k_gemm3<<<nb_w, 256>>>(W3, n);
    k_final<<<nb_n, 256>>>(b3, out, n);
}

// round 9
// speedup vs baseline: 1.5629x; 1.0090x over previous
#include <cuda_runtime.h>
#include <stdint.h>

#define NMAX 50000
#define EMAX 800000
#define DIM 128

// ---------------- scratch (static device globals; no allocation) ----------------
__device__ float g_buf0[(size_t)NMAX * DIM];   // GEMM output H
__device__ float g_buf1[(size_t)NMAX * DIM];   // aggregated / activation buffer
__device__ float g_h3[NMAX * 2];
__device__ float g_dis[NMAX];
__device__ int   g_cnt[NMAX];
__device__ int   g_starts[NMAX];
__device__ int   g_cursor[NMAX];
__device__ long long g_csr[EMAX];              // packed: low32 = src, high32 = w bits
__device__ int   g_total;

// ---------------- JAX Threefry-2x32 (20 rounds) ----------------
__host__ __device__ __forceinline__ void tf2x32(uint32_t k0, uint32_t k1,
                                                uint32_t x0, uint32_t x1,
                                                uint32_t& o0, uint32_t& o1) {
    uint32_t ks2 = k0 ^ k1 ^ 0x1BD11BDAu;
    x0 += k0; x1 += k1;
#define TFROT(a, b, r) { a += b; b = ((b << (r)) | (b >> (32 - (r)))); b ^= a; }
    TFROT(x0, x1, 13) TFROT(x0, x1, 15) TFROT(x0, x1, 26) TFROT(x0, x1, 6)
    x0 += k1;  x1 += ks2 + 1u;
    TFROT(x0, x1, 17) TFROT(x0, x1, 29) TFROT(x0, x1, 16) TFROT(x0, x1, 24)
    x0 += ks2; x1 += k0 + 2u;
    TFROT(x0, x1, 13) TFROT(x0, x1, 15) TFROT(x0, x1, 26) TFROT(x0, x1, 6)
    x0 += k0;  x1 += k1 + 3u;
    TFROT(x0, x1, 17) TFROT(x0, x1, 29) TFROT(x0, x1, 16) TFROT(x0, x1, 24)
    x0 += k1;  x1 += ks2 + 4u;
    TFROT(x0, x1, 13) TFROT(x0, x1, 15) TFROT(x0, x1, 26) TFROT(x0, x1, 6)
    x0 += ks2; x1 += k0 + 5u;
#undef TFROT
    o0 = x0; o1 = x1;
}

// dropout decision for flat element index i under key (ka,kb): true => keep
__device__ __forceinline__ bool drop_keep(uint32_t ka, uint32_t kb, uint32_t i) {
    uint32_t y0, y1;
    tf2x32(ka, kb, 0u, i, y0, y1);
    uint32_t bits = y0 ^ y1;
    float u = __uint_as_float((bits >> 9) | 0x3f800000u) - 1.0f;
    return u < 0.5f;
}

// ---------------- graph prep ----------------
__global__ void k_zero_cnt(int n) {
    int i = blockIdx.x * blockDim.x + threadIdx.x;
    if (i == 0) g_total = 0;
    if (i < n) g_cnt[i] = 0;
}

// int4-vectorized degree count (4 edges per thread) + scalar tail
__global__ void k_count(const int* __restrict__ ei, int E) {
    int q = blockIdx.x * blockDim.x + threadIdx.x;
    int E4 = E >> 2;
    if (q < E4) {
        int4 d = ((const int4*)(ei + E))[q];
        atomicAdd(&g_cnt[d.x], 1);
        atomicAdd(&g_cnt[d.y], 1);
        atomicAdd(&g_cnt[d.z], 1);
        atomicAdd(&g_cnt[d.w], 1);
    } else {
        int r = (E4 << 2) + (q - E4);
        if (r < E) atomicAdd(&g_cnt[ei[E + r]], 1);
    }
}

// dis + region reservation with warp-aggregated atomic (one ATOMG per warp,
// not per thread: avoids single-address atomic serialization ~0.854 cyc/lane)
__global__ void k_disres(int n) {
    int i = blockIdx.x * blockDim.x + threadIdx.x;
    int lane = threadIdx.x & 31;
    int c = (i < n) ? g_cnt[i] : 0;
    if (i < n) g_dis[i] = rsqrtf((float)(c + 1));
    // inclusive warp scan of c
    int pfx = c;
#pragma unroll
    for (int off = 1; off < 32; off <<= 1) {
        int t = __shfl_up_sync(0xffffffffu, pfx, off);
        if (lane >= off) pfx += t;
    }
    int tot = __shfl_sync(0xffffffffu, pfx, 31);
    int base = 0;
    if (lane == 31) base = atomicAdd(&g_total, tot);
    base = __shfl_sync(0xffffffffu, base, 31);
    int st = base + pfx - c;
    if (i < n) { g_starts[i] = st; g_cursor[i] = st; }
}

// scatter: 2 edges per thread, packed 8-byte CSR entry (one sector per edge
// instead of two)
__global__ void k_scatter(const int* __restrict__ ei, int E) {
    int q = blockIdx.x * blockDim.x + threadIdx.x;
    int e0 = q * 2;
    if (e0 >= E) return;
    if (e0 + 1 < E) {
        int2 s2 = ((const int2*)ei)[q];
        int2 d2 = ((const int2*)(ei + E))[q];
        float w0 = g_dis[s2.x] * g_dis[d2.x];
        int p0 = atomicAdd(&g_cursor[d2.x], 1);
        g_csr[p0] = ((long long)(unsigned)__float_as_int(w0) << 32) | (unsigned)s2.x;
        float w1 = g_dis[s2.y] * g_dis[d2.y];
        int p1 = atomicAdd(&g_cursor[d2.y], 1);
        g_csr[p1] = ((long long)(unsigned)__float_as_int(w1) << 32) | (unsigned)s2.y;
    } else {
        int s = ei[e0];
        int d = ei[E + e0];
        float w = g_dis[s] * g_dis[d];
        int p = atomicAdd(&g_cursor[d], 1);
        g_csr[p] = ((long long)(unsigned)__float_as_int(w) << 32) | (unsigned)s;
    }
}

// ---------------- GEMM: g_buf0[nrows,128] = X[nrows,128] @ W[128,128] ----------------
// 128 rows x 128 cols per block, 256 threads, 8x8 register tile, K chunked by 16.
#define XS_STRIDE 136   // floats; multiple of 4 for aligned float4 reads

__global__ void k_gemm128(const float* __restrict__ Xext,
                          const float* __restrict__ W, int nrows) {
    __shared__ float Ws[16 * 128];            // [16 k][128 cols]
    __shared__ float Xs[16 * XS_STRIDE];      // transposed: [16 k][128 rows]

    const float* X = Xext ? Xext : g_buf1;
    float* H = g_buf0;

    int t = threadIdx.x;
    int row0 = blockIdx.x * 128;
    int tx = t & 15;    // col group (8 cols)
    int ty = t >> 4;    // row group (8 rows)

    float acc[8][8];
#pragma unroll
    for (int i = 0; i < 8; i++)
#pragma unroll
        for (int j = 0; j < 8; j++) acc[i][j] = 0.f;

    for (int c = 0; c < 8; c++) {             // K chunks of 16
        const float4* Wg = (const float4*)(W + c * 16 * 128);
        float4* Wsv = (float4*)Ws;
        Wsv[t] = Wg[t];
        Wsv[t + 256] = Wg[t + 256];

#pragma unroll
        for (int i = 0; i < 2; i++) {
            int q = t + i * 256;              // 0..511
            int r = q >> 2;                   // 0..127
            int kk = (q & 3) * 4;             // 0,4,8,12
            float4 v = make_float4(0.f, 0.f, 0.f, 0.f);
            if (row0 + r < nrows)
                v = *(const float4*)(X + (size_t)(row0 + r) * DIM + c * 16 + kk);
            Xs[(kk + 0) * XS_STRIDE + r] = v.x;
            Xs[(kk + 1) * XS_STRIDE + r] = v.y;
            Xs[(kk + 2) * XS_STRIDE + r] = v.z;
            Xs[(kk + 3) * XS_STRIDE + r] = v.w;
        }
        __syncthreads();

#pragma unroll
        for (int k = 0; k < 16; k++) {
            float4 xa = *(const float4*)&Xs[k * XS_STRIDE + ty * 8];
            float4 xb = *(const float4*)&Xs[k * XS_STRIDE + ty * 8 + 4];
            float4 wa = *(const float4*)&Ws[k * 128 + tx * 8];
            float4 wb = *(const float4*)&Ws[k * 128 + tx * 8 + 4];
            float xr[8] = {xa.x, xa.y, xa.z, xa.w, xb.x, xb.y, xb.z, xb.w};
            float wr[8] = {wa.x, wa.y, wa.z, wa.w, wb.x, wb.y, wb.z, wb.w};
#pragma unroll
            for (int i = 0; i < 8; i++)
#pragma unroll
                for (int j = 0; j < 8; j++) acc[i][j] += xr[i] * wr[j];
        }
        __syncthreads();
    }

#pragma unroll
    for (int i = 0; i < 8; i++) {
        int r = row0 + ty * 8 + i;
        if (r < nrows) {
            float4 o0 = make_float4(acc[i][0], acc[i][1], acc[i][2], acc[i][3]);
            float4 o1 = make_float4(acc[i][4], acc[i][5], acc[i][6], acc[i][7]);
            *(float4*)(H + (size_t)r * DIM + tx * 8) = o0;
            *(float4*)(H + (size_t)r * DIM + tx * 8 + 4) = o1;
        }
    }
}

// ------- aggregation + bias + (optional) leaky_relu + exact-JAX dropout -------
// g_buf1[v] = f( b + dis[v]^2*g_buf0[v] + sum_e w*g_buf0[src] )
__global__ void k_agg128(const float* __restrict__ bias, int n,
                         int doAct, uint32_t ka, uint32_t kb) {
    const float* H = g_buf0;
    float* OUT = g_buf1;
    int g = blockIdx.x * blockDim.x + threadIdx.x;
    int v = g >> 5;
    if (v >= n) return;
    int lane = g & 31;
    int s0 = g_starts[v];
    int cnt = g_cnt[v];

    float4 acc = make_float4(0.f, 0.f, 0.f, 0.f);
    for (int base = 0; base < cnt; base += 32) {
        int si = 0; float wi = 0.f;
        if (base + lane < cnt) {
            long long p = g_csr[s0 + base + lane];
            si = (int)(unsigned)(p & 0xffffffffll);
            wi = __int_as_float((int)(p >> 32));
        }
        int m = min(32, cnt - base);
        for (int j = 0; j < m; j++) {
            int s = __shfl_sync(0xffffffffu, si, j);
            float w = __shfl_sync(0xffffffffu, wi, j);
            float4 hv = *(const float4*)(H + (size_t)s * DIM + lane * 4);
            acc.x += w * hv.x; acc.y += w * hv.y;
            acc.z += w * hv.z; acc.w += w * hv.w;
        }
    }
    float dv = g_dis[v];
    float ws = dv * dv;
    float4 hv = *(const float4*)(H + (size_t)v * DIM + lane * 4);
    float4 bv = *(const float4*)(bias + lane * 4);
    acc.x += ws * hv.x + bv.x;
    acc.y += ws * hv.y + bv.y;
    acc.z += ws * hv.z + bv.z;
    acc.w += ws * hv.w + bv.w;

    if (doAct) {
        uint32_t i0 = (uint32_t)v * DIM + lane * 4;
        float a[4] = {acc.x, acc.y, acc.z, acc.w};
#pragma unroll
        for (int c2 = 0; c2 < 4; c2++) {
            float vv = a[c2];
            vv = (vv >= 0.f) ? vv : 0.01f * vv;          // leaky_relu
            a[c2] = drop_keep(ka, kb, i0 + c2) ? (vv + vv) : 0.f;  // p=0.5
        }
        acc.x = a[0]; acc.y = a[1]; acc.z = a[2]; acc.w = a[3];
    }
    *(float4*)(OUT + (size_t)v * DIM + lane * 4) = acc;
}

// ---------------- layer 3: g_h3 = g_buf1[N,128] @ W3[128,2], warp per node ----------------
__global__ void k_gemm3(const float* __restrict__ W3, int n) {
    const float* X = g_buf1;
    int g = blockIdx.x * blockDim.x + threadIdx.x;
    int v = g >> 5;
    if (v >= n) return;
    int lane = g & 31;
    float4 xv = *(const float4*)(X + (size_t)v * DIM + lane * 4);
    float4 wA = *(const float4*)(W3 + lane * 8);
    float4 wB = *(const float4*)(W3 + lane * 8 + 4);
    float a0 = xv.x * wA.x + xv.y * wA.z + xv.z * wB.x + xv.w * wB.z;
    float a1 = xv.x * wA.y + xv.y * wA.w + xv.z * wB.y + xv.w * wB.w;
#pragma unroll
    for (int off = 16; off > 0; off >>= 1) {
        a0 += __shfl_xor_sync(0xffffffffu, a0, off);
        a1 += __shfl_xor_sync(0xffffffffu, a1, off);
    }
    if (lane == 0) { g_h3[v * 2] = a0; g_h3[v * 2 + 1] = a1; }
}

// ---------------- final aggregation + bias + log_softmax ----------------
__global__ void k_final(const float* __restrict__ b3, float* __restrict__ out, int n) {
    int v = blockIdx.x * blockDim.x + threadIdx.x;
    if (v >= n) return;
    int s0 = g_starts[v];
    int e0 = s0 + g_cnt[v];
    float a0 = 0.f, a1 = 0.f;
    for (int i = s0; i < e0; i++) {
        long long p = g_csr[i];
        int s = (int)(unsigned)(p & 0xffffffffll);
        float w = __int_as_float((int)(p >> 32));
        a0 += w * g_h3[s * 2];
        a1 += w * g_h3[s * 2 + 1];
    }
    float dv = g_dis[v];
    float ws = dv * dv;
    a0 += ws * g_h3[v * 2]     + b3[0];
    a1 += ws * g_h3[v * 2 + 1] + b3[1];
    float m = fmaxf(a0, a1);
    float lse = m + logf(expf(a0 - m) + expf(a1 - m));
    out[v * 2]     = a0 - lse;
    out[v * 2 + 1] = a1 - lse;
}

// ---------------- launch (pure kernel launches; graph-capture safe) ----------------
extern "C" void kernel_launch(void* const* d_in, const int* in_sizes, int n_in,
                              void* d_out, int out_size) {
    const float* x  = (const float*)d_in[0];
    const int*   ei = (const int*)d_in[1];     // int32 (JAX x64 disabled)
    const float* W1 = (const float*)d_in[2];
    const float* b1 = (const float*)d_in[3];
    const float* W2 = (const float*)d_in[4];
    const float* b2 = (const float*)d_in[5];
    const float* W3 = (const float*)d_in[6];
    const float* b3 = (const float*)d_in[7];
    float* out = (float*)d_out;

    int n = in_sizes[0] / DIM;      // 50000
    int E = in_sizes[1] / 2;        // 800000

    // JAX: dkey = key(42); k1, k2 = split(dkey)  [partitionable fold-like split]
    uint32_t k1a, k1b, k2a, k2b;
    tf2x32(0u, 42u, 0u, 0u, k1a, k1b);
    tf2x32(0u, 42u, 0u, 1u, k2a, k2b);

    int nb_n = (n + 255) / 256;
    int nb_w = (n * 32 + 255) / 256;   // warp-per-node grids
    int nb_g = (n + 127) / 128;
    int nb_c = (E / 4 + 3 + 255) / 256;
    int nb_s = ((E + 1) / 2 + 255) / 256;

    // graph prep
    k_zero_cnt<<<nb_n, 256>>>(n);
    k_count<<<nb_c, 256>>>(ei, E);
    k_disres<<<nb_n, 256>>>(n);
    k_scatter<<<nb_s, 256>>>(ei, E);

    // layer 1 (agg fuses bias + leaky_relu + dropout)
    k_gemm128<<<nb_g, 256>>>(x, W1, n);
    k_agg128<<<nb_w, 256>>>(b1, n, 1, k1a, k1b);

    // layer 2
    k_gemm128<<<nb_g, 256>>>(nullptr, W2, n);
    k_agg128<<<nb_w, 256>>>(b2, n, 1, k2a, k2b);

    // layer 3 + log_softmax
    k_gemm3<<<nb_w, 256>>>(W3, n);
    k_final<<<nb_n, 256>>>(b3, out, n);
}

// round 10
// speedup vs baseline: 1.7510x; 1.1203x over previous
#include <cuda_runtime.h>
#include <stdint.h>

#define NMAX 50000
#define EMAX 800000
#define DIM 128

// ---------------- scratch (static device globals; no allocation) ----------------
__device__ float g_buf0[(size_t)NMAX * DIM];   // GEMM output H
__device__ float g_buf1[(size_t)NMAX * DIM];   // aggregated / activation buffer
__device__ float g_h3[NMAX * 2];
__device__ float g_dis[NMAX];
__device__ int   g_cnt[NMAX];
__device__ int   g_starts[NMAX];
__device__ int   g_cursor[NMAX];
__device__ long long g_csr[EMAX];              // packed: low32 = src, high32 = w bits
__device__ int   g_total;

// ---------------- packed f32x2 helpers (Blackwell FFMA2 — PTX-only) ----------------
__device__ __forceinline__ unsigned long long packf2(float lo, float hi) {
    unsigned long long r;
    asm("mov.b64 %0, {%1, %2};" : "=l"(r) : "f"(lo), "f"(hi));
    return r;
}
__device__ __forceinline__ void fmaf2(unsigned long long& d,
                                      unsigned long long a, unsigned long long b) {
    asm("fma.rn.f32x2 %0, %1, %2, %0;" : "+l"(d) : "l"(a), "l"(b));
}
__device__ __forceinline__ float2 unpackf2(unsigned long long v) {
    float lo, hi;
    asm("mov.b64 {%0, %1}, %2;" : "=f"(lo), "=f"(hi) : "l"(v));
    return make_float2(lo, hi);
}

// ---------------- JAX Threefry-2x32 (20 rounds) ----------------
__host__ __device__ __forceinline__ void tf2x32(uint32_t k0, uint32_t k1,
                                                uint32_t x0, uint32_t x1,
                                                uint32_t& o0, uint32_t& o1) {
    uint32_t ks2 = k0 ^ k1 ^ 0x1BD11BDAu;
    x0 += k0; x1 += k1;
#define TFROT(a, b, r) { a += b; b = ((b << (r)) | (b >> (32 - (r)))); b ^= a; }
    TFROT(x0, x1, 13) TFROT(x0, x1, 15) TFROT(x0, x1, 26) TFROT(x0, x1, 6)
    x0 += k1;  x1 += ks2 + 1u;
    TFROT(x0, x1, 17) TFROT(x0, x1, 29) TFROT(x0, x1, 16) TFROT(x0, x1, 24)
    x0 += ks2; x1 += k0 + 2u;
    TFROT(x0, x1, 13) TFROT(x0, x1, 15) TFROT(x0, x1, 26) TFROT(x0, x1, 6)
    x0 += k0;  x1 += k1 + 3u;
    TFROT(x0, x1, 17) TFROT(x0, x1, 29) TFROT(x0, x1, 16) TFROT(x0, x1, 24)
    x0 += k1;  x1 += ks2 + 4u;
    TFROT(x0, x1, 13) TFROT(x0, x1, 15) TFROT(x0, x1, 26) TFROT(x0, x1, 6)
    x0 += ks2; x1 += k0 + 5u;
#undef TFROT
    o0 = x0; o1 = x1;
}

__device__ __forceinline__ bool drop_keep(uint32_t ka, uint32_t kb, uint32_t i) {
    uint32_t y0, y1;
    tf2x32(ka, kb, 0u, i, y0, y1);
    uint32_t bits = y0 ^ y1;
    float u = __uint_as_float((bits >> 9) | 0x3f800000u) - 1.0f;
    return u < 0.5f;
}

// ---------------- graph prep ----------------
__global__ void k_zero_cnt(int n) {
    int i = blockIdx.x * blockDim.x + threadIdx.x;
    if (i == 0) g_total = 0;
    if (i < n) g_cnt[i] = 0;
}

__global__ void k_count(const int* __restrict__ ei, int E) {
    int q = blockIdx.x * blockDim.x + threadIdx.x;
    int E4 = E >> 2;
    if (q < E4) {
        int4 d = ((const int4*)(ei + E))[q];
        atomicAdd(&g_cnt[d.x], 1);
        atomicAdd(&g_cnt[d.y], 1);
        atomicAdd(&g_cnt[d.z], 1);
        atomicAdd(&g_cnt[d.w], 1);
    } else {
        int r = (E4 << 2) + (q - E4);
        if (r < E) atomicAdd(&g_cnt[ei[E + r]], 1);
    }
}

// dis + region reservation with warp-aggregated atomic
__global__ void k_disres(int n) {
    int i = blockIdx.x * blockDim.x + threadIdx.x;
    int lane = threadIdx.x & 31;
    int c = (i < n) ? g_cnt[i] : 0;
    if (i < n) g_dis[i] = rsqrtf((float)(c + 1));
    int pfx = c;
#pragma unroll
    for (int off = 1; off < 32; off <<= 1) {
        int t = __shfl_up_sync(0xffffffffu, pfx, off);
        if (lane >= off) pfx += t;
    }
    int tot = __shfl_sync(0xffffffffu, pfx, 31);
    int base = 0;
    if (lane == 31) base = atomicAdd(&g_total, tot);
    base = __shfl_sync(0xffffffffu, base, 31);
    int st = base + pfx - c;
    if (i < n) { g_starts[i] = st; g_cursor[i] = st; }
}

// scatter: 4 edges per thread (MLP), packed 8-byte CSR entries
__global__ void k_scatter(const int* __restrict__ ei, int E) {
    int q = blockIdx.x * blockDim.x + threadIdx.x;
    int E4 = E >> 2;
    if (q < E4) {
        int4 s4 = ((const int4*)ei)[q];
        int4 d4 = ((const int4*)(ei + E))[q];
        // batch the random dis loads first for MLP
        float ds0 = g_dis[s4.x], ds1 = g_dis[s4.y], ds2 = g_dis[s4.z], ds3 = g_dis[s4.w];
        float dd0 = g_dis[d4.x], dd1 = g_dis[d4.y], dd2 = g_dis[d4.z], dd3 = g_dis[d4.w];
        int p0 = atomicAdd(&g_cursor[d4.x], 1);
        int p1 = atomicAdd(&g_cursor[d4.y], 1);
        int p2 = atomicAdd(&g_cursor[d4.z], 1);
        int p3 = atomicAdd(&g_cursor[d4.w], 1);
        g_csr[p0] = ((long long)(unsigned)__float_as_int(ds0 * dd0) << 32) | (unsigned)s4.x;
        g_csr[p1] = ((long long)(unsigned)__float_as_int(ds1 * dd1) << 32) | (unsigned)s4.y;
        g_csr[p2] = ((long long)(unsigned)__float_as_int(ds2 * dd2) << 32) | (unsigned)s4.z;
        g_csr[p3] = ((long long)(unsigned)__float_as_int(ds3 * dd3) << 32) | (unsigned)s4.w;
    } else {
        int r = (E4 << 2) + (q - E4);
        if (r < E) {
            int s = ei[r];
            int d = ei[E + r];
            float w = g_dis[s] * g_dis[d];
            int p = atomicAdd(&g_cursor[d], 1);
            g_csr[p] = ((long long)(unsigned)__float_as_int(w) << 32) | (unsigned)s;
        }
    }
}

// ---------------- GEMM: g_buf0[nrows,128] = X[nrows,128] @ W[128,128] ----------------
// 128x128 tile, 256 threads, 8x8 per thread via packed f32x2 FFMA2
// (row-pairs x 8 cols => 32 FFMA2 per k). Bit-identical to scalar FFMA.
#define XS_STRIDE 136

__global__ void __launch_bounds__(256, 2)
k_gemm128(const float* __restrict__ Xext, const float* __restrict__ W, int nrows) {
    __shared__ float Ws[16 * 128];
    __shared__ float Xs[16 * XS_STRIDE];

    const float* X = Xext ? Xext : g_buf1;
    float* H = g_buf0;

    int t = threadIdx.x;
    int row0 = blockIdx.x * 128;
    int tx = t & 15;
    int ty = t >> 4;

    unsigned long long accp[4][8];   // row-pairs (2p,2p+1) x 8 cols
#pragma unroll
    for (int p = 0; p < 4; p++)
#pragma unroll
        for (int j = 0; j < 8; j++) accp[p][j] = 0ull;

    for (int c = 0; c < 8; c++) {
        const float4* Wg = (const float4*)(W + c * 16 * 128);
        float4* Wsv = (float4*)Ws;
        Wsv[t] = Wg[t];
        Wsv[t + 256] = Wg[t + 256];

#pragma unroll
        for (int i = 0; i < 2; i++) {
            int q = t + i * 256;
            int r = q >> 2;
            int kk = (q & 3) * 4;
            float4 v = make_float4(0.f, 0.f, 0.f, 0.f);
            if (row0 + r < nrows)
                v = *(const float4*)(X + (size_t)(row0 + r) * DIM + c * 16 + kk);
            Xs[(kk + 0) * XS_STRIDE + r] = v.x;
            Xs[(kk + 1) * XS_STRIDE + r] = v.y;
            Xs[(kk + 2) * XS_STRIDE + r] = v.z;
            Xs[(kk + 3) * XS_STRIDE + r] = v.w;
        }
        __syncthreads();

#pragma unroll
        for (int k = 0; k < 16; k++) {
            float4 xa = *(const float4*)&Xs[k * XS_STRIDE + ty * 8];
            float4 xb = *(const float4*)&Xs[k * XS_STRIDE + ty * 8 + 4];
            float4 wa = *(const float4*)&Ws[k * 128 + tx * 8];
            float4 wb = *(const float4*)&Ws[k * 128 + tx * 8 + 4];
            unsigned long long xp[4], wd[8];
            xp[0] = packf2(xa.x, xa.y);
            xp[1] = packf2(xa.z, xa.w);
            xp[2] = packf2(xb.x, xb.y);
            xp[3] = packf2(xb.z, xb.w);
            wd[0] = packf2(wa.x, wa.x);
            wd[1] = packf2(wa.y, wa.y);
            wd[2] = packf2(wa.z, wa.z);
            wd[3] = packf2(wa.w, wa.w);
            wd[4] = packf2(wb.x, wb.x);
            wd[5] = packf2(wb.y, wb.y);
            wd[6] = packf2(wb.z, wb.z);
            wd[7] = packf2(wb.w, wb.w);
#pragma unroll
            for (int p = 0; p < 4; p++)
#pragma unroll
                for (int j = 0; j < 8; j++) fmaf2(accp[p][j], xp[p], wd[j]);
        }
        __syncthreads();
    }

#pragma unroll
    for (int p = 0; p < 4; p++) {
        float lo[8], hi[8];
#pragma unroll
        for (int j = 0; j < 8; j++) {
            float2 u = unpackf2(accp[p][j]);
            lo[j] = u.x; hi[j] = u.y;
        }
        int r0 = row0 + ty * 8 + 2 * p;
        if (r0 < nrows) {
            *(float4*)(H + (size_t)r0 * DIM + tx * 8) = make_float4(lo[0], lo[1], lo[2], lo[3]);
            *(float4*)(H + (size_t)r0 * DIM + tx * 8 + 4) = make_float4(lo[4], lo[5], lo[6], lo[7]);
        }
        if (r0 + 1 < nrows) {
            *(float4*)(H + (size_t)(r0 + 1) * DIM + tx * 8) = make_float4(hi[0], hi[1], hi[2], hi[3]);
            *(float4*)(H + (size_t)(r0 + 1) * DIM + tx * 8 + 4) = make_float4(hi[4], hi[5], hi[6], hi[7]);
        }
    }
}

// ------- aggregation + bias + leaky_relu + dropout (+ optional fused x@W3) -------
// If W3 == nullptr: g_buf1[v] = f(agg).  Else: g_h3[v] = f(agg) @ W3 (no g_buf1 write).
__global__ void k_agg128(const float* __restrict__ bias, const float* __restrict__ W3,
                         int n, uint32_t ka, uint32_t kb) {
    const float* H = g_buf0;
    int g = blockIdx.x * blockDim.x + threadIdx.x;
    int v = g >> 5;
    if (v >= n) return;
    int lane = g & 31;
    int s0 = g_starts[v];
    int cnt = g_cnt[v];

    float4 acc = make_float4(0.f, 0.f, 0.f, 0.f);
    for (int base = 0; base < cnt; base += 32) {
        int si = 0; float wi = 0.f;
        if (base + lane < cnt) {
            long long p = g_csr[s0 + base + lane];
            si = (int)(unsigned)(p & 0xffffffffll);
            wi = __int_as_float((int)(p >> 32));
        }
        int m = min(32, cnt - base);
        for (int j = 0; j < m; j++) {
            int s = __shfl_sync(0xffffffffu, si, j);
            float w = __shfl_sync(0xffffffffu, wi, j);
            float4 hv = *(const float4*)(H + (size_t)s * DIM + lane * 4);
            acc.x += w * hv.x; acc.y += w * hv.y;
            acc.z += w * hv.z; acc.w += w * hv.w;
        }
    }
    float dv = g_dis[v];
    float ws = dv * dv;
    float4 hv = *(const float4*)(H + (size_t)v * DIM + lane * 4);
    float4 bv = *(const float4*)(bias + lane * 4);
    acc.x += ws * hv.x + bv.x;
    acc.y += ws * hv.y + bv.y;
    acc.z += ws * hv.z + bv.z;
    acc.w += ws * hv.w + bv.w;

    // leaky_relu + exact-JAX dropout
    {
        uint32_t i0 = (uint32_t)v * DIM + lane * 4;
        float a[4] = {acc.x, acc.y, acc.z, acc.w};
#pragma unroll
        for (int c2 = 0; c2 < 4; c2++) {
            float vv = a[c2];
            vv = (vv >= 0.f) ? vv : 0.01f * vv;
            a[c2] = drop_keep(ka, kb, i0 + c2) ? (vv + vv) : 0.f;
        }
        acc.x = a[0]; acc.y = a[1]; acc.z = a[2]; acc.w = a[3];
    }

    if (W3 == nullptr) {
        *(float4*)(g_buf1 + (size_t)v * DIM + lane * 4) = acc;
    } else {
        // fused layer-3 GEMM: this warp holds the full 128-dim row
        float4 wA = *(const float4*)(W3 + lane * 8);
        float4 wB = *(const float4*)(W3 + lane * 8 + 4);
        float a0 = acc.x * wA.x + acc.y * wA.z + acc.z * wB.x + acc.w * wB.z;
        float a1 = acc.x * wA.y + acc.y * wA.w + acc.z * wB.y + acc.w * wB.w;
#pragma unroll
        for (int off = 16; off > 0; off >>= 1) {
            a0 += __shfl_xor_sync(0xffffffffu, a0, off);
            a1 += __shfl_xor_sync(0xffffffffu, a1, off);
        }
        if (lane == 0) { g_h3[v * 2] = a0; g_h3[v * 2 + 1] = a1; }
    }
}

// ---------------- final aggregation + bias + log_softmax ----------------
__global__ void k_final(const float* __restrict__ b3, float* __restrict__ out, int n) {
    int v = blockIdx.x * blockDim.x + threadIdx.x;
    if (v >= n) return;
    int s0 = g_starts[v];
    int e0 = s0 + g_cnt[v];
    float a0 = 0.f, a1 = 0.f;
    for (int i = s0; i < e0; i++) {
        long long p = g_csr[i];
        int s = (int)(unsigned)(p & 0xffffffffll);
        float w = __int_as_float((int)(p >> 32));
        a0 += w * g_h3[s * 2];
        a1 += w * g_h3[s * 2 + 1];
    }
    float dv = g_dis[v];
    float ws = dv * dv;
    a0 += ws * g_h3[v * 2]     + b3[0];
    a1 += ws * g_h3[v * 2 + 1] + b3[1];
    float m = fmaxf(a0, a1);
    float lse = m + logf(expf(a0 - m) + expf(a1 - m));
    out[v * 2]     = a0 - lse;
    out[v * 2 + 1] = a1 - lse;
}

// ---------------- launch (fork-join overlap; graph-capture safe) ----------------
extern "C" void kernel_launch(void* const* d_in, const int* in_sizes, int n_in,
                              void* d_out, int out_size) {
    const float* x  = (const float*)d_in[0];
    const int*   ei = (const int*)d_in[1];
    const float* W1 = (const float*)d_in[2];
    const float* b1 = (const float*)d_in[3];
    const float* W2 = (const float*)d_in[4];
    const float* b2 = (const float*)d_in[5];
    const float* W3 = (const float*)d_in[6];
    const float* b3 = (const float*)d_in[7];
    float* out = (float*)d_out;

    int n = in_sizes[0] / DIM;      // 50000
    int E = in_sizes[1] / 2;        // 800000

    uint32_t k1a, k1b, k2a, k2b;
    tf2x32(0u, 42u, 0u, 0u, k1a, k1b);
    tf2x32(0u, 42u, 0u, 1u, k2a, k2b);

    static cudaStream_t s_side = nullptr;
    static cudaEvent_t ev_fork = nullptr, ev_join = nullptr;
    if (s_side == nullptr) {
        cudaStreamCreateWithFlags(&s_side, cudaStreamNonBlocking);
        cudaEventCreateWithFlags(&ev_fork, cudaEventDisableTiming);
        cudaEventCreateWithFlags(&ev_join, cudaEventDisableTiming);
    }

    int nb_n = (n + 255) / 256;
    int nb_w = (n * 32 + 255) / 256;
    int nb_g = (n + 127) / 128;
    int E4 = E >> 2;
    int nb_q = (E4 + (E & 3) + 255) / 256;

    // fork: CSR prep on side stream, concurrent with GEMM1 on main stream
    cudaEventRecord(ev_fork, 0);
    cudaStreamWaitEvent(s_side, ev_fork, 0);
    k_zero_cnt<<<nb_n, 256, 0, s_side>>>(n);
    k_count<<<nb_q, 256, 0, s_side>>>(ei, E);
    k_disres<<<nb_n, 256, 0, s_side>>>(n);
    k_scatter<<<nb_q, 256, 0, s_side>>>(ei, E);
    cudaEventRecord(ev_join, s_side);

    k_gemm128<<<nb_g, 256>>>(x, W1, n);           // main stream, overlaps prep

    cudaStreamWaitEvent(0, ev_join, 0);           // join before agg1

    // layer 1
    k_agg128<<<nb_w, 256>>>(b1, nullptr, n, k1a, k1b);
    // layer 2 (+ fused layer-3 GEMM in agg epilogue)
    k_gemm128<<<nb_g, 256>>>(nullptr, W2, n);
    k_agg128<<<nb_w, 256>>>(b2, W3, n, k2a, k2b);
    // final aggregation + log_softmax
    k_final<<<nb_n, 256>>>(b3, out, n);
}